// round 1
// baseline (speedup 1.0000x reference)
#include <cuda_runtime.h>
#include <cstdint>

// Problem constants
#define N_TOK 262144
#define DIM   64
#define KCB   512
#define GAMMA 0.99f

#define TPB    256      // threads per block in assign kernel (1 token / thread)
#define TILE_K 128      // codebook rows per smem tile (4 tiles total)

// Scratch (allocation-free rule: __device__ globals)
__device__ float g_cs[KCB * DIM];   // segment sum of x
__device__ float g_cn[KCB];         // counts
__device__ float g_bias[KCB];       // 0.5*||vq_k||^2

// ---------------- packed f32x2 helpers (sm_100a) ----------------
__device__ __forceinline__ unsigned long long pk2(float lo, float hi) {
    unsigned long long r;
    asm("mov.b64 %0, {%1, %2};" : "=l"(r) : "f"(lo), "f"(hi));
    return r;
}
__device__ __forceinline__ void unpk2(unsigned long long v, float& lo, float& hi) {
    asm("mov.b64 {%0, %1}, %2;" : "=f"(lo), "=f"(hi) : "l"(v));
}
__device__ __forceinline__ unsigned long long fma2(unsigned long long a,
                                                   unsigned long long b,
                                                   unsigned long long c) {
    unsigned long long d;
    asm("fma.rn.f32x2 %0, %1, %2, %3;" : "=l"(d) : "l"(a), "l"(b), "l"(c));
    return d;
}
__device__ __forceinline__ unsigned long long add2(unsigned long long a,
                                                   unsigned long long b) {
    unsigned long long d;
    asm("add.rn.f32x2 %0, %1, %2;" : "=l"(d) : "l"(a), "l"(b));
    return d;
}

// ---------------- init: zero scratch + compute bias ----------------
// grid = KCB blocks, 64 threads
__global__ void init_kernel(const float* __restrict__ vq) {
    int k = blockIdx.x;
    int d = threadIdx.x;
    g_cs[k * DIM + d] = 0.0f;
    float v = vq[k * DIM + d];
    float s = v * v;
    __shared__ float sh[2];
    #pragma unroll
    for (int o = 16; o > 0; o >>= 1) s += __shfl_down_sync(0xffffffffu, s, o);
    if ((d & 31) == 0) sh[d >> 5] = s;
    __syncthreads();
    if (d == 0) {
        g_bias[k] = 0.5f * (sh[0] + sh[1]);
        g_cn[k] = 0.0f;
    }
}

// ---------------- main: argmax(x.v - bias), gather, atomics ----------------
__global__ void __launch_bounds__(TPB, 2) assign_kernel(
    const float* __restrict__ x,
    const float* __restrict__ vq,
    float* __restrict__ q_out)
{
    __shared__ __align__(16) float s_vq[TILE_K * DIM];   // 32 KB
    __shared__ float s_bias[TILE_K];

    const int tok = blockIdx.x * TPB + threadIdx.x;

    // Load this token's x row into registers, packed as 32 f32x2
    unsigned long long xr[DIM / 2];
    {
        const float4* xrow = reinterpret_cast<const float4*>(x + (size_t)tok * DIM);
        #pragma unroll
        for (int i = 0; i < DIM / 4; i++) {
            float4 v = xrow[i];
            xr[2 * i]     = pk2(v.x, v.y);
            xr[2 * i + 1] = pk2(v.z, v.w);
        }
    }

    float bestScore = -3.4e38f;
    int   bestK = 0;

    for (int tile = 0; tile < KCB / TILE_K; tile++) {
        __syncthreads();   // protect previous tile from overwrite
        // cooperative load: TILE_K*DIM floats = 2048 float4
        {
            const float4* src = reinterpret_cast<const float4*>(vq + tile * TILE_K * DIM);
            float4* dst = reinterpret_cast<float4*>(s_vq);
            #pragma unroll
            for (int i = threadIdx.x; i < TILE_K * DIM / 4; i += TPB) dst[i] = src[i];
            if (threadIdx.x < TILE_K) s_bias[threadIdx.x] = g_bias[tile * TILE_K + threadIdx.x];
        }
        __syncthreads();

        #pragma unroll 1
        for (int k = 0; k < TILE_K; k++) {
            const unsigned long long* v2 =
                reinterpret_cast<const unsigned long long*>(s_vq + k * DIM);
            unsigned long long a0 = 0ull, a1 = 0ull, a2 = 0ull, a3 = 0ull;
            #pragma unroll
            for (int j = 0; j < DIM / 2; j += 4) {
                a0 = fma2(xr[j],     v2[j],     a0);
                a1 = fma2(xr[j + 1], v2[j + 1], a1);
                a2 = fma2(xr[j + 2], v2[j + 2], a2);
                a3 = fma2(xr[j + 3], v2[j + 3], a3);
            }
            a0 = add2(a0, a1);
            a2 = add2(a2, a3);
            a0 = add2(a0, a2);
            float lo, hi;
            unpk2(a0, lo, hi);
            float score = (lo + hi) - s_bias[k];
            if (score > bestScore) { bestScore = score; bestK = tile * TILE_K + k; }
        }
    }

    // quantized = vq[bestK]  (gather from global; codebook is L2-resident)
    {
        const float4* vrow = reinterpret_cast<const float4*>(vq + (size_t)bestK * DIM);
        float4* qrow = reinterpret_cast<float4*>(q_out + (size_t)tok * DIM);
        #pragma unroll
        for (int i = 0; i < DIM / 4; i++) qrow[i] = vrow[i];
    }

    // segment sums via global reductions
    {
        float* csrow = g_cs + (size_t)bestK * DIM;
        #pragma unroll
        for (int j = 0; j < DIM / 2; j++) {
            float lo, hi;
            unpk2(xr[j], lo, hi);
            atomicAdd(csrow + 2 * j,     lo);
            atomicAdd(csrow + 2 * j + 1, hi);
        }
        atomicAdd(&g_cn[bestK], 1.0f);
    }
}

// ---------------- finalize: EMA update + outputs ----------------
// grid = KCB blocks, 64 threads
__global__ void finalize_kernel(
    const float* __restrict__ centroid_sum,
    const float* __restrict__ centroid_n,
    float* __restrict__ out_vq,
    float* __restrict__ out_cs,
    float* __restrict__ out_cn)
{
    int k = blockIdx.x;
    int d = threadIdx.x;
    float cs_new = centroid_sum[k * DIM + d] * GAMMA + g_cs[k * DIM + d] * (1.0f - GAMMA);
    float cn_new = centroid_n[k] * GAMMA + g_cn[k] * (1.0f - GAMMA);
    out_vq[k * DIM + d] = cs_new / cn_new;
    out_cs[k * DIM + d] = cs_new;
    if (d == 0) out_cn[k] = cn_new;
}

extern "C" void kernel_launch(void* const* d_in, const int* in_sizes, int n_in,
                              void* d_out, int out_size) {
    const float* x  = (const float*)d_in[0];   // [N, 64]
    const float* vq = (const float*)d_in[1];   // [512, 64]
    const float* cs = (const float*)d_in[2];   // [512, 64]
    const float* cn = (const float*)d_in[3];   // [512]

    float* out = (float*)d_out;
    float* q_out   = out;                                   // [N, 64]
    float* vq_out  = out + (size_t)N_TOK * DIM;             // [512, 64]
    float* cs_out  = vq_out + (size_t)KCB * DIM;            // [512, 64]
    float* cn_out  = cs_out + (size_t)KCB * DIM;            // [512]

    init_kernel<<<KCB, DIM>>>(vq);
    assign_kernel<<<N_TOK / TPB, TPB>>>(x, vq, q_out);
    // Guard against an unexpected output layout (only quantized requested)
    if (out_size >= N_TOK * DIM + 2 * KCB * DIM + KCB) {
        finalize_kernel<<<KCB, DIM>>>(cs, cn, vq_out, cs_out, cn_out);
    }
}

// round 2
// speedup vs baseline: 1.1613x; 1.1613x over previous
#include <cuda_runtime.h>
#include <cstdint>

// Problem constants
#define N_TOK 262144
#define DIM   64
#define KCB   512
#define GAMMA 0.99f

#define TPB     128     // threads per block (assign)
#define TOKPT   2       // tokens per thread
#define TOK_CTA (TPB * TOKPT)   // 256 tokens per CTA
#define TILE_K  128     // codebook rows per smem tile (4 tiles)

typedef unsigned long long ull;

// Scratch (allocation-free rule: __device__ globals; zero-init at module load,
// re-zeroed by finalize_kernel after each consumption so graph replays are correct)
__device__ float g_cs[KCB * DIM];
__device__ float g_cn[KCB];

// ---------------- packed f32x2 helpers (sm_100a) ----------------
__device__ __forceinline__ ull pk2(float lo, float hi) {
    ull r;
    asm("mov.b64 %0, {%1, %2};" : "=l"(r) : "f"(lo), "f"(hi));
    return r;
}
__device__ __forceinline__ void unpk2(ull v, float& lo, float& hi) {
    asm("mov.b64 {%0, %1}, %2;" : "=f"(lo), "=f"(hi) : "l"(v));
}
__device__ __forceinline__ ull fma2(ull a, ull b, ull c) {
    ull d;
    asm("fma.rn.f32x2 %0, %1, %2, %3;" : "=l"(d) : "l"(a), "l"(b), "l"(c));
    return d;
}
__device__ __forceinline__ ull add2(ull a, ull b) {
    ull d;
    asm("add.rn.f32x2 %0, %1, %2;" : "=l"(d) : "l"(a), "l"(b));
    return d;
}

// ---------------- assign: argmax(x.v - 0.5||v||^2), gather, segment atomics ----
__global__ void __launch_bounds__(TPB, 2) assign_kernel(
    const float* __restrict__ x,
    const float* __restrict__ vq,
    float* __restrict__ q_out)
{
    __shared__ __align__(16) float s_vq[TILE_K * DIM];   // 32 KB
    __shared__ float s_bias[TILE_K];

    const int tid  = threadIdx.x;
    const int tokA = blockIdx.x * TOK_CTA + tid;          // token A
    const int tokB = tokA + TPB;                          // token B

    // Load both token rows into registers, packed as f32x2
    ull xa[DIM / 2], xb[DIM / 2];
    {
        const float4* ra = reinterpret_cast<const float4*>(x + (size_t)tokA * DIM);
        const float4* rb = reinterpret_cast<const float4*>(x + (size_t)tokB * DIM);
        #pragma unroll
        for (int i = 0; i < DIM / 4; i++) {
            float4 a = ra[i];
            xa[2 * i]     = pk2(a.x, a.y);
            xa[2 * i + 1] = pk2(a.z, a.w);
            float4 b = rb[i];
            xb[2 * i]     = pk2(b.x, b.y);
            xb[2 * i + 1] = pk2(b.z, b.w);
        }
    }

    float bestA = -3.4e38f, bestB = -3.4e38f;
    int   kA = 0, kB = 0;

    for (int tile = 0; tile < KCB / TILE_K; tile++) {
        __syncthreads();   // previous tile fully consumed
        // Cooperative tile load: 2048 float4, strided (conflict-free STS.128)
        {
            const float4* src = reinterpret_cast<const float4*>(vq + (size_t)tile * TILE_K * DIM);
            float4* dst = reinterpret_cast<float4*>(s_vq);
            #pragma unroll
            for (int i = tid; i < TILE_K * DIM / 4; i += TPB) dst[i] = src[i];
        }
        __syncthreads();
        // Bias for codeword `tid` of this tile, lane-rotated reads (conflict-free)
        {
            const float* row = s_vq + tid * DIM;
            const int lane = tid & 31;
            float s = 0.0f;
            #pragma unroll
            for (int j = 0; j < DIM; j++) {
                float v = row[(j + lane) & (DIM - 1)];
                s = fmaf(v, v, s);
            }
            s_bias[tid] = 0.5f * s;
        }
        __syncthreads();

        #pragma unroll 1
        for (int k = 0; k < TILE_K; k++) {
            const ulonglong2* v2 = reinterpret_cast<const ulonglong2*>(s_vq + k * DIM);
            ull a0 = 0ull, a1 = 0ull, a2 = 0ull, a3 = 0ull;
            ull b0 = 0ull, b1 = 0ull, b2 = 0ull, b3 = 0ull;
            #pragma unroll
            for (int j = 0; j < DIM / 4; j++) {      // 16 x LDS.128
                ulonglong2 w = v2[j];                 // 2 f32x2 codeword values
                if ((j & 1) == 0) {
                    a0 = fma2(xa[2 * j],     w.x, a0);
                    a1 = fma2(xa[2 * j + 1], w.y, a1);
                    b0 = fma2(xb[2 * j],     w.x, b0);
                    b1 = fma2(xb[2 * j + 1], w.y, b1);
                } else {
                    a2 = fma2(xa[2 * j],     w.x, a2);
                    a3 = fma2(xa[2 * j + 1], w.y, a3);
                    b2 = fma2(xb[2 * j],     w.x, b2);
                    b3 = fma2(xb[2 * j + 1], w.y, b3);
                }
            }
            float bias = s_bias[k];
            a0 = add2(add2(a0, a1), add2(a2, a3));
            b0 = add2(add2(b0, b1), add2(b2, b3));
            float lo, hi;
            unpk2(a0, lo, hi);
            float sA = (lo + hi) - bias;
            unpk2(b0, lo, hi);
            float sB = (lo + hi) - bias;
            int kk = tile * TILE_K + k;
            if (sA > bestA) { bestA = sA; kA = kk; }
            if (sB > bestB) { bestB = sB; kB = kk; }
        }
    }

    // quantized = vq[best]  (codebook is L2-resident)
    {
        const float4* va = reinterpret_cast<const float4*>(vq + (size_t)kA * DIM);
        const float4* vb = reinterpret_cast<const float4*>(vq + (size_t)kB * DIM);
        float4* qa = reinterpret_cast<float4*>(q_out + (size_t)tokA * DIM);
        float4* qb = reinterpret_cast<float4*>(q_out + (size_t)tokB * DIM);
        #pragma unroll
        for (int i = 0; i < DIM / 4; i++) { qa[i] = va[i]; qb[i] = vb[i]; }
    }

    // segment sums (return value unused -> RED)
    {
        float* ca = g_cs + (size_t)kA * DIM;
        float* cb = g_cs + (size_t)kB * DIM;
        #pragma unroll
        for (int j = 0; j < DIM / 2; j++) {
            float lo, hi;
            unpk2(xa[j], lo, hi);
            atomicAdd(ca + 2 * j, lo);
            atomicAdd(ca + 2 * j + 1, hi);
            unpk2(xb[j], lo, hi);
            atomicAdd(cb + 2 * j, lo);
            atomicAdd(cb + 2 * j + 1, hi);
        }
        atomicAdd(&g_cn[kA], 1.0f);
        atomicAdd(&g_cn[kB], 1.0f);
    }
}

// ---------------- finalize: EMA update + outputs, then re-zero scratch --------
// grid = KCB blocks, 64 threads
__global__ void finalize_kernel(
    const float* __restrict__ centroid_sum,
    const float* __restrict__ centroid_n,
    float* __restrict__ out_vq,
    float* __restrict__ out_cs,
    float* __restrict__ out_cn)
{
    int k = blockIdx.x;
    int d = threadIdx.x;
    float cs_acc = g_cs[k * DIM + d];
    float cn_acc = g_cn[k];
    __syncthreads();                 // all reads done before re-zero
    g_cs[k * DIM + d] = 0.0f;
    if (d == 0) g_cn[k] = 0.0f;

    float cs_new = centroid_sum[k * DIM + d] * GAMMA + cs_acc * (1.0f - GAMMA);
    float cn_new = centroid_n[k] * GAMMA + cn_acc * (1.0f - GAMMA);
    out_vq[k * DIM + d] = cs_new / cn_new;
    out_cs[k * DIM + d] = cs_new;
    if (d == 0) out_cn[k] = cn_new;
}

extern "C" void kernel_launch(void* const* d_in, const int* in_sizes, int n_in,
                              void* d_out, int out_size) {
    const float* x  = (const float*)d_in[0];   // [N, 64]
    const float* vq = (const float*)d_in[1];   // [512, 64]
    const float* cs = (const float*)d_in[2];   // [512, 64]
    const float* cn = (const float*)d_in[3];   // [512]

    float* out    = (float*)d_out;
    float* q_out  = out;                        // [N, 64]
    float* vq_out = out + (size_t)N_TOK * DIM;  // [512, 64]
    float* cs_out = vq_out + (size_t)KCB * DIM; // [512, 64]
    float* cn_out = cs_out + (size_t)KCB * DIM; // [512]

    assign_kernel<<<N_TOK / TOK_CTA, TPB>>>(x, vq, q_out);
    finalize_kernel<<<KCB, DIM>>>(cs, cn, vq_out, cs_out, cn_out);
}